// round 2
// baseline (speedup 1.0000x reference)
#include <cuda_runtime.h>
#include <cstdint>

typedef unsigned long long ull;

#define NQ 8
#define DIM 256
#define NW 16
#define NB 16
#define NCIRC (NB*NW)     // 256
#define NROTS 64
#define EMB 512
#define NVOCAB 50257
#define NOUT_OP (NB*NVOCAB)

// ---------------- scratch (no allocations allowed) ----------------
__device__ float  g_wparams[NCIRC*NROTS];
__device__ float2 g_coeffs[NW];
__device__ float2 g_states[NCIRC*DIM];
__device__ float2 g_work[NB*DIM];
__device__ float2 g_acc[NB*DIM];
__device__ float  g_fp[NB];
__device__ float  g_hT[EMB*NB];   // [k][b]

// ---------------- f32x2 helpers (sm_100+ packed fp32) ----------------
__device__ __forceinline__ ull pack2(float a, float b){
    ull r; asm("mov.b64 %0, {%1,%2};" : "=l"(r) : "f"(a), "f"(b)); return r;
}
__device__ __forceinline__ void unpack2(ull v, float &a, float &b){
    asm("mov.b64 {%0,%1}, %2;" : "=f"(a), "=f"(b) : "l"(v));
}
__device__ __forceinline__ void fma2(ull &d, ull a, ull b){
    asm("fma.rn.f32x2 %0, %1, %2, %0;" : "+l"(d) : "l"(a), "l"(b));
}
__device__ __forceinline__ ull add2(ull a, ull b){
    ull r; asm("add.rn.f32x2 %0, %1, %2;" : "=l"(r) : "l"(a), "l"(b)); return r;
}

// ---------------- prep: normalized complex mix coefficients ----------------
__global__ void prep_kernel(const float* __restrict__ mix){
    int t = threadIdx.x; // 32
    float re = 0.f, im = 0.f, a = 0.f;
    if (t < NW){ re = mix[2*t]; im = mix[2*t+1]; a = sqrtf(re*re + im*im); }
    float s = a;
    #pragma unroll
    for (int o = 16; o; o >>= 1) s += __shfl_xor_sync(0xffffffffu, s, o);
    float inv = 1.f / fmaxf(s, 1e-12f);
    if (t < NW) g_coeffs[t] = make_float2(re*inv, im*inv);
}

// ---------------- wparams: emb gather + small GEMM ----------------
__global__ void wparams_kernel(const int* __restrict__ x,
                               const float* __restrict__ embW,
                               const float* __restrict__ e2rW,
                               const float* __restrict__ e2rb){
    __shared__ float emb[EMB];
    int bid = blockIdx.x;      // b*NW + w, 256 blocks
    int t = threadIdx.x;       // 64
    int row = x[bid];
    const float* er = embW + (size_t)row * EMB;
    #pragma unroll
    for (int k = t; k < EMB; k += 64) emb[k] = er[k];
    __syncthreads();
    const float4* wr4 = (const float4*)(e2rW + (size_t)t * EMB);
    float acc = e2rb[t];
    #pragma unroll 8
    for (int k = 0; k < EMB/4; k++){
        float4 w4 = wr4[k];
        acc += emb[4*k]*w4.x + emb[4*k+1]*w4.y + emb[4*k+2]*w4.z + emb[4*k+3]*w4.w;
    }
    g_wparams[bid*NROTS + t] = acc;
}

// ---------------- gate primitives on smem state ----------------
__device__ __forceinline__ void gate_ry(float2* st, float c, float s, int p, int tid){
    int j = tid; // 0..127
    int i0 = ((j >> p) << (p+1)) | (j & ((1 << p) - 1));
    int i1 = i0 | (1 << p);
    float2 a0 = st[i0], a1 = st[i1];
    st[i0] = make_float2(c*a0.x - s*a1.x, c*a0.y - s*a1.y);
    st[i1] = make_float2(s*a0.x + c*a1.x, s*a0.y + c*a1.y);
}

__device__ __forceinline__ void gate_crx(float2* st, float c, float s, int pc, int pt, int tid){
    if (tid < 64){
        int lo = pc < pt ? pc : pt;
        int hi = pc < pt ? pt : pc;
        int i = tid; // 6 free bits
        i = ((i >> lo) << (lo+1)) | (i & ((1 << lo) - 1));
        i = ((i >> hi) << (hi+1)) | (i & ((1 << hi) - 1));
        int i0 = i | (1 << pc);
        int i1 = i0 | (1 << pt);
        float2 a0 = st[i0], a1 = st[i1];
        st[i0] = make_float2(c*a0.x + s*a1.y, c*a0.y - s*a1.x);
        st[i1] = make_float2(c*a1.x + s*a0.y, c*a1.y - s*a0.x);
    }
}

// sim14 circuit: wire i <-> bit (7-i)
__device__ void run_sim(float2* st, const float* cs, const float* sn, int layers, int tid){
    int idx = 0;
    for (int L = 0; L < layers; L++){
        #pragma unroll
        for (int i = 0; i < 8; i++){ gate_ry(st, cs[idx], sn[idx], 7-i, tid); idx++; __syncthreads(); }
        #pragma unroll
        for (int i = 7; i >= 0; i--){ gate_crx(st, cs[idx], sn[idx], 7-i, 7-((i+1)&7), tid); idx++; __syncthreads(); }
        #pragma unroll
        for (int i = 0; i < 8; i++){ gate_ry(st, cs[idx], sn[idx], 7-i, tid); idx++; __syncthreads(); }
        { int i = 7; gate_crx(st, cs[idx], sn[idx], 7-i, 7-((i+7)&7), tid); idx++; __syncthreads(); }
        #pragma unroll
        for (int i = 0; i < 7; i++){ gate_crx(st, cs[idx], sn[idx], 7-i, 7-((i+7)&7), tid); idx++; __syncthreads(); }
    }
}

// ---------------- per-circuit simulation (one block = one circuit) ----------------
__global__ void sim_kernel(int first){
    __shared__ float2 st[DIM];
    __shared__ float cs[NROTS], sn[NROTS];
    int bid = blockIdx.x;   // 256
    int t = threadIdx.x;    // 128
    int b = bid >> 4;
    if (t < NROTS){
        float th = g_wparams[bid*NROTS + t] * 0.5f;
        sincosf(th, &sn[t], &cs[t]);
    }
    if (first){
        st[t]       = make_float2(t == 0 ? 1.f : 0.f, 0.f);
        st[t + 128] = make_float2(0.f, 0.f);
    } else {
        st[t]       = g_work[b*DIM + t];
        st[t + 128] = g_work[b*DIM + t + 128];
    }
    __syncthreads();
    run_sim(st, cs, sn, 2, t);
    g_states[bid*DIM + t]       = st[t];
    g_states[bid*DIM + t + 128] = st[t + 128];
}

// ---------------- combine over words + polynomial accumulate ----------------
__global__ void combine_kernel(const float* __restrict__ poly, int d){
    int b = blockIdx.x;   // 16
    int i = threadIdx.x;  // 256
    __shared__ float2 cf[NW];
    if (i < NW) cf[i] = g_coeffs[i];
    __syncthreads();
    float2 acc = make_float2(0.f, 0.f);
    #pragma unroll
    for (int w = 0; w < NW; w++){
        float2 c = cf[w];
        float2 s = g_states[(b*NW + w)*DIM + i];
        acc.x += c.x*s.x - c.y*s.y;
        acc.y += c.x*s.y + c.y*s.x;
    }
    g_work[b*DIM + i] = acc;
    float pd = poly[d];
    if (d == 1){
        float p0 = poly[0];
        g_acc[b*DIM + i] = make_float2((i == 0 ? p0 : 0.f) + pd*acc.x, pd*acc.y);
    } else {
        float2 a = g_acc[b*DIM + i];
        g_acc[b*DIM + i] = make_float2(a.x + pd*acc.x, a.y + pd*acc.y);
    }
}

// ---------------- final: normalize, qff circuit, measure, FF1 ----------------
__global__ void final_kernel(const float* __restrict__ poly,
                             const float* __restrict__ qff,
                             const float* __restrict__ ff1W,
                             const float* __restrict__ ff1b){
    __shared__ float2 st[DIM];
    __shared__ float cs[32], sn[32];
    __shared__ float red[12];
    __shared__ float exps[24];
    __shared__ float bcast;
    int b = blockIdx.x;   // 16
    int t = threadIdx.x;  // 128
    int lane = t & 31, wid = t >> 5;

    float psum = fabsf(poly[0]) + fabsf(poly[1]) + fabsf(poly[2]) + fabsf(poly[3]);
    float invp = 1.f / psum;
    float2 m0 = g_acc[b*DIM + t];
    float2 m1 = g_acc[b*DIM + t + 128];
    m0.x *= invp; m0.y *= invp; m1.x *= invp; m1.y *= invp;

    float loc = m0.x*m0.x + m0.y*m0.y + m1.x*m1.x + m1.y*m1.y;
    #pragma unroll
    for (int o = 16; o; o >>= 1) loc += __shfl_xor_sync(0xffffffffu, loc, o);
    if (lane == 0) red[wid] = loc;
    if (t < 32) sincosf(qff[t]*0.5f, &sn[t], &cs[t]);
    __syncthreads();
    if (t == 0){
        float fp = sqrtf(red[0] + red[1] + red[2] + red[3]);
        g_fp[b] = fp;
        bcast = 1.f / fmaxf(fp, 1e-12f);
    }
    __syncthreads();
    float inv = bcast;
    st[t]       = make_float2(m0.x*inv, m0.y*inv);
    st[t + 128] = make_float2(m1.x*inv, m1.y*inv);
    __syncthreads();

    run_sim(st, cs, sn, 1, t);

    // measure X/Y/Z per wire
    for (int w = 0; w < 8; w++){
        int p = 7 - w;
        int i0 = ((t >> p) << (p+1)) | (t & ((1 << p) - 1));
        int i1 = i0 | (1 << p);
        float2 a0 = st[i0], a1 = st[i1];
        float cr = a0.x*a1.x + a0.y*a1.y;
        float ci = a0.x*a1.y - a0.y*a1.x;
        float zz = (a0.x*a0.x + a0.y*a0.y) - (a1.x*a1.x + a1.y*a1.y);
        #pragma unroll
        for (int o = 16; o; o >>= 1){
            cr += __shfl_xor_sync(0xffffffffu, cr, o);
            ci += __shfl_xor_sync(0xffffffffu, ci, o);
            zz += __shfl_xor_sync(0xffffffffu, zz, o);
        }
        if (lane == 0){ red[wid*3] = cr; red[wid*3+1] = ci; red[wid*3+2] = zz; }
        __syncthreads();
        if (t == 0){
            exps[w]      = 2.f*(red[0] + red[3] + red[6] + red[9]);
            exps[8 + w]  = 2.f*(red[1] + red[4] + red[7] + red[10]);
            exps[16 + w] =      red[2] + red[5] + red[8] + red[11];
        }
        __syncthreads();
    }

    // FF1: h[j] = relu(exps . ff1W[j,:] + b[j]), store transposed [k][b]
    #pragma unroll
    for (int jj = 0; jj < 4; jj++){
        int j = t + jj*128;
        float a = ff1b[j];
        const float* wr = ff1W + j*24;
        #pragma unroll
        for (int m = 0; m < 24; m++) a += exps[m] * wr[m];
        g_hT[j*NB + b] = fmaxf(a, 0.f);
    }
}

// ---------------- FF2: 16 x 50257 x 512 GEMM via packed f32x2 ----------------
// block = 256 thr (8 warps); warp-tile = 8 v x 8 b (4 b-pairs); block covers 32 v x 16 b
__global__ void __launch_bounds__(256, 2) ff2_kernel(const float* __restrict__ W,
                                                     const float* __restrict__ bias,
                                                     float* __restrict__ out,
                                                     int write_scalar){
    __shared__ float2 hp[8][EMB];   // hp[bj][k] = (h[2bj][k], h[2bj+1][k]) — conflict-free LDS.64
    int t = threadIdx.x;
    for (int idx = t; idx < 8*EMB; idx += 256){
        int bj = idx >> 9, k = idx & 511;
        hp[bj][k] = make_float2(g_hT[k*NB + 2*bj], g_hT[k*NB + 2*bj + 1]);
    }
    if (write_scalar && blockIdx.x == 0 && t == 0){
        float s = 0.f;
        #pragma unroll
        for (int b = 0; b < NB; b++) s += g_fp[b];
        out[NOUT_OP] = s * (1.f/16.f);
    }
    __syncthreads();

    int wid = t >> 5, lane = t & 31;
    int vbase  = blockIdx.x*32 + (wid >> 1)*8;
    int bjbase = (wid & 1)*4;

    ull acc[8][4];
    #pragma unroll
    for (int vi = 0; vi < 8; vi++)
        #pragma unroll
        for (int j = 0; j < 4; j++) acc[vi][j] = 0ULL;

    #pragma unroll 1
    for (int kc = 0; kc < 16; kc++){
        int k = kc*32 + lane;
        float wv[8];
        #pragma unroll
        for (int vi = 0; vi < 8; vi++){
            int v = vbase + vi;
            wv[vi] = (v < NVOCAB) ? W[(size_t)v*EMB + k] : 0.f;
        }
        ull h2[4];
        #pragma unroll
        for (int j = 0; j < 4; j++)
            h2[j] = *(const ull*)&hp[bjbase + j][k];
        #pragma unroll
        for (int vi = 0; vi < 8; vi++){
            ull w2 = pack2(wv[vi], wv[vi]);
            #pragma unroll
            for (int j = 0; j < 4; j++) fma2(acc[vi][j], w2, h2[j]);
        }
    }

    // butterfly reduce across 32 lanes (each lane accumulated k = lane mod 32)
    #pragma unroll
    for (int o = 16; o; o >>= 1){
        #pragma unroll
        for (int vi = 0; vi < 8; vi++)
            #pragma unroll
            for (int j = 0; j < 4; j++)
                acc[vi][j] = add2(acc[vi][j], __shfl_xor_sync(0xffffffffu, acc[vi][j], o));
    }

    // each lane writes one (vi, bj) pair
    int vi = lane & 7;
    int jl = lane >> 3;             // 0..3
    int bj = bjbase + jl;
    int v = vbase + vi;
    if (v < NVOCAB){
        float bv = bias[v];
        float lo, hi; unpack2(acc[vi][jl], lo, hi);
        out[(size_t)(2*bj)*NVOCAB + v]     = lo + bv;
        out[(size_t)(2*bj + 1)*NVOCAB + v] = hi + bv;
    }
}

// ---------------- launch ----------------
extern "C" void kernel_launch(void* const* d_in, const int* in_sizes, int n_in,
                              void* d_out, int out_size){
    const int*   x    = (const int*)  d_in[0];
    const float* embW = (const float*)d_in[1];
    const float* e2rW = (const float*)d_in[2];
    const float* e2rb = (const float*)d_in[3];
    const float* poly = (const float*)d_in[4];
    const float* mix  = (const float*)d_in[5];
    const float* qff  = (const float*)d_in[6];
    const float* ff1W = (const float*)d_in[7];
    const float* ff1b = (const float*)d_in[8];
    const float* ff2W = (const float*)d_in[9];
    const float* ff2b = (const float*)d_in[10];
    float* out = (float*)d_out;

    prep_kernel<<<1, 32>>>(mix);
    wparams_kernel<<<NCIRC, 64>>>(x, embW, e2rW, e2rb);

    sim_kernel<<<NCIRC, 128>>>(1);
    combine_kernel<<<NB, 256>>>(poly, 1);
    sim_kernel<<<NCIRC, 128>>>(0);
    combine_kernel<<<NB, 256>>>(poly, 2);
    sim_kernel<<<NCIRC, 128>>>(0);
    combine_kernel<<<NB, 256>>>(poly, 3);

    final_kernel<<<NB, 128>>>(poly, qff, ff1W, ff1b);

    int ws = (out_size > NOUT_OP) ? 1 : 0;
    ff2_kernel<<<(NVOCAB + 31)/32, 256>>>(ff2W, ff2b, out, ws);
}